// round 8
// baseline (speedup 1.0000x reference)
#include <cuda_runtime.h>
#include <math.h>

#define NN 50000
#define EE 800000
#define NF 256
#define NH 4
#define ND 64
#define NC 16

// ---------------- device scratch (static, no allocation) ----------------
__device__ float g_feat1[NN * NF];      // x @ W1          [N,256]
__device__ float g_h[NN * NF];          // elu(aggr1+b1)   [N,256]
__device__ float g_feat2[NN * NC];      // h @ W2          [N,16]
__device__ float g_el1[NN * NH];
__device__ float g_er1[NN * NH];
__device__ float g_el2[NN];
__device__ float g_er2[NN];
__device__ int   g_deg[NN];
__device__ int   g_cur[NN];
__device__ int   g_off[NN + 1];
__device__ int   g_col[EE];             // src node per CSR slot (sorted by dst)

// ---------------- CSR build ----------------
__global__ void k_clear() {
    int i = blockIdx.x * blockDim.x + threadIdx.x;
    if (i < NN) { g_deg[i] = 0; g_cur[i] = 0; }
}

__global__ void k_hist(const int* __restrict__ dst) {
    int e = blockIdx.x * blockDim.x + threadIdx.x;
    if (e < EE) atomicAdd(&g_deg[dst[e]], 1);
}

// single-block shuffle-based exclusive scan over g_deg -> g_off
__global__ void k_scan() {
    __shared__ int warpsum[32];
    __shared__ int carry_s;
    int t = threadIdx.x, lane = t & 31, wid = t >> 5;
    if (t == 0) carry_s = 0;
    __syncthreads();
    for (int base = 0; base < NN; base += 1024) {
        int i = base + t;
        int v = (i < NN) ? g_deg[i] : 0;
        int x = v;
        #pragma unroll
        for (int o = 1; o < 32; o <<= 1) {
            int y = __shfl_up_sync(0xffffffffu, x, o);
            if (lane >= o) x += y;
        }
        if (lane == 31) warpsum[wid] = x;
        __syncthreads();
        if (wid == 0) {
            int w = warpsum[lane];
            #pragma unroll
            for (int o = 1; o < 32; o <<= 1) {
                int y = __shfl_up_sync(0xffffffffu, w, o);
                if (lane >= o) w += y;
            }
            warpsum[lane] = w;
        }
        __syncthreads();
        int pre  = (wid > 0) ? warpsum[wid - 1] : 0;
        int incl = x + pre;
        if (i < NN) g_off[i] = carry_s + incl - v;
        int total = warpsum[31];
        __syncthreads();
        if (t == 0) carry_s += total;
        __syncthreads();
    }
    if (threadIdx.x == 0) g_off[NN] = carry_s;
}

__global__ void k_scatter(const int* __restrict__ src, const int* __restrict__ dst) {
    int e = blockIdx.x * blockDim.x + threadIdx.x;
    if (e < EE) {
        int d = dst[e];
        int p = g_off[d] + atomicAdd(&g_cur[d], 1);
        g_col[p] = src[e];
    }
}

// ---------------- GEMM1: feat1 = x @ W1  (M=50000, N=256, K=256, fp32) ----------------
__global__ void __launch_bounds__(128) k_gemm1(const float* __restrict__ A,
                                               const float* __restrict__ B) {
    __shared__ float As[16][68];
    __shared__ float Bs[16][68];
    int tid = threadIdx.x;
    int ty = tid >> 3;          // 0..15 -> row quad
    int tx = tid & 7;           // 0..7  -> col octet
    int m0 = blockIdx.y * 64;
    int n0 = blockIdx.x * 64;

    float c[4][8];
    #pragma unroll
    for (int i = 0; i < 4; i++)
        #pragma unroll
        for (int j = 0; j < 8; j++) c[i][j] = 0.f;

    int arow = tid >> 2;        // 0..31
    int acol = (tid & 3) * 4;   // 0,4,8,12
    int brow = tid >> 4;        // 0..7
    int bcol = (tid & 15) * 4;  // 0..60

    for (int kt = 0; kt < 256; kt += 16) {
        #pragma unroll
        for (int rr = 0; rr < 2; rr++) {
            int m = arow + rr * 32;
            int g = m0 + m;
            float4 v = make_float4(0.f, 0.f, 0.f, 0.f);
            if (g < NN) v = *(const float4*)(A + g * 256 + kt + acol);
            As[acol + 0][m] = v.x; As[acol + 1][m] = v.y;
            As[acol + 2][m] = v.z; As[acol + 3][m] = v.w;
        }
        #pragma unroll
        for (int rr = 0; rr < 2; rr++) {
            int k = brow + rr * 8;
            float4 v = *(const float4*)(B + (kt + k) * 256 + n0 + bcol);
            *(float4*)&Bs[k][bcol] = v;
        }
        __syncthreads();
        #pragma unroll
        for (int kk = 0; kk < 16; kk++) {
            float4 a  = *(const float4*)&As[kk][ty * 4];
            float4 b0 = *(const float4*)&Bs[kk][tx * 8];
            float4 b1 = *(const float4*)&Bs[kk][tx * 8 + 4];
            float av[4] = {a.x, a.y, a.z, a.w};
            float bv[8] = {b0.x, b0.y, b0.z, b0.w, b1.x, b1.y, b1.z, b1.w};
            #pragma unroll
            for (int i = 0; i < 4; i++)
                #pragma unroll
                for (int j = 0; j < 8; j++)
                    c[i][j] += av[i] * bv[j];
        }
        __syncthreads();
    }
    #pragma unroll
    for (int i = 0; i < 4; i++) {
        int g = m0 + ty * 4 + i;
        if (g < NN) {
            float* o = g_feat1 + g * 256 + n0 + tx * 8;
            *(float4*)(o)     = make_float4(c[i][0], c[i][1], c[i][2], c[i][3]);
            *(float4*)(o + 4) = make_float4(c[i][4], c[i][5], c[i][6], c[i][7]);
        }
    }
}

// ---------------- per-node attention scalars (layer 1) ----------------
__global__ void k_el1(const float* __restrict__ al1, const float* __restrict__ ar1) {
    int idx = blockIdx.x * blockDim.x + threadIdx.x;
    if (idx >= NN * NH) return;
    int n = idx >> 2, h = idx & 3;
    const float4* f = (const float4*)(g_feat1 + n * 256 + h * 64);
    const float4* a = (const float4*)(al1 + h * 64);
    const float4* r = (const float4*)(ar1 + h * 64);
    float sl = 0.f, sr = 0.f;
    #pragma unroll
    for (int i = 0; i < 16; i++) {
        float4 v = f[i], A = a[i], R = r[i];
        sl += v.x * A.x + v.y * A.y + v.z * A.z + v.w * A.w;
        sr += v.x * R.x + v.y * R.y + v.z * R.z + v.w * R.w;
    }
    g_el1[idx] = sl;
    g_er1[idx] = sr;
}

// ---------------- layer-1 fused edge-softmax + aggregate + bias + ELU ----------------
__global__ void __launch_bounds__(128) k_aggr1(const float* __restrict__ b1) {
    int n = blockIdx.x;
    int t = threadIdx.x;
    int beg = g_off[n], deg = g_off[n + 1] - beg;

    __shared__ float s_max[4], s_inv[4];
    __shared__ float s_alpha[128][4];
    __shared__ int   s_src[128];

    if (deg == 0) {
        float o0 = b1[t];       o0 = o0 > 0.f ? o0 : expf(o0) - 1.f;
        float o1 = b1[t + 128]; o1 = o1 > 0.f ? o1 : expf(o1) - 1.f;
        g_h[n * 256 + t] = o0;
        g_h[n * 256 + t + 128] = o1;
        return;
    }

    float4 ern = *(const float4*)(g_er1 + n * 4);

    if (t < 32) {
        float m0 = -1e30f, m1 = -1e30f, m2 = -1e30f, m3 = -1e30f;
        for (int i = t; i < deg; i += 32) {
            int s = g_col[beg + i];
            float4 el = *(const float4*)(g_el1 + s * 4);
            float e0 = el.x + ern.x; e0 = e0 > 0.f ? e0 : 0.2f * e0;
            float e1 = el.y + ern.y; e1 = e1 > 0.f ? e1 : 0.2f * e1;
            float e2 = el.z + ern.z; e2 = e2 > 0.f ? e2 : 0.2f * e2;
            float e3 = el.w + ern.w; e3 = e3 > 0.f ? e3 : 0.2f * e3;
            m0 = fmaxf(m0, e0); m1 = fmaxf(m1, e1);
            m2 = fmaxf(m2, e2); m3 = fmaxf(m3, e3);
        }
        #pragma unroll
        for (int o = 16; o; o >>= 1) {
            m0 = fmaxf(m0, __shfl_xor_sync(0xffffffffu, m0, o));
            m1 = fmaxf(m1, __shfl_xor_sync(0xffffffffu, m1, o));
            m2 = fmaxf(m2, __shfl_xor_sync(0xffffffffu, m2, o));
            m3 = fmaxf(m3, __shfl_xor_sync(0xffffffffu, m3, o));
        }
        float d0 = 0.f, d1 = 0.f, d2 = 0.f, d3 = 0.f;
        for (int i = t; i < deg; i += 32) {
            int s = g_col[beg + i];
            float4 el = *(const float4*)(g_el1 + s * 4);
            float e0 = el.x + ern.x; e0 = e0 > 0.f ? e0 : 0.2f * e0;
            float e1 = el.y + ern.y; e1 = e1 > 0.f ? e1 : 0.2f * e1;
            float e2 = el.z + ern.z; e2 = e2 > 0.f ? e2 : 0.2f * e2;
            float e3 = el.w + ern.w; e3 = e3 > 0.f ? e3 : 0.2f * e3;
            d0 += expf(e0 - m0); d1 += expf(e1 - m1);
            d2 += expf(e2 - m2); d3 += expf(e3 - m3);
        }
        #pragma unroll
        for (int o = 16; o; o >>= 1) {
            d0 += __shfl_xor_sync(0xffffffffu, d0, o);
            d1 += __shfl_xor_sync(0xffffffffu, d1, o);
            d2 += __shfl_xor_sync(0xffffffffu, d2, o);
            d3 += __shfl_xor_sync(0xffffffffu, d3, o);
        }
        if (t == 0) {
            s_max[0] = m0; s_max[1] = m1; s_max[2] = m2; s_max[3] = m3;
            s_inv[0] = 1.f / d0; s_inv[1] = 1.f / d1;
            s_inv[2] = 1.f / d2; s_inv[3] = 1.f / d3;
        }
    }
    __syncthreads();

    float acc0 = 0.f, acc1 = 0.f;
    int h0 = t >> 6;        // 0 or 1
    int h1 = h0 + 2;        // 2 or 3

    for (int base = 0; base < deg; base += 128) {
        int i = base + t;
        if (i < deg) {
            int s = g_col[beg + i];
            s_src[t] = s;
            float4 el = *(const float4*)(g_el1 + s * 4);
            float e0 = el.x + ern.x; e0 = e0 > 0.f ? e0 : 0.2f * e0;
            float e1 = el.y + ern.y; e1 = e1 > 0.f ? e1 : 0.2f * e1;
            float e2 = el.z + ern.z; e2 = e2 > 0.f ? e2 : 0.2f * e2;
            float e3 = el.w + ern.w; e3 = e3 > 0.f ? e3 : 0.2f * e3;
            s_alpha[t][0] = expf(e0 - s_max[0]) * s_inv[0];
            s_alpha[t][1] = expf(e1 - s_max[1]) * s_inv[1];
            s_alpha[t][2] = expf(e2 - s_max[2]) * s_inv[2];
            s_alpha[t][3] = expf(e3 - s_max[3]) * s_inv[3];
        }
        __syncthreads();
        int cnt = min(128, deg - base);
        #pragma unroll 4
        for (int j = 0; j < cnt; j++) {
            const float* row = g_feat1 + s_src[j] * 256;
            acc0 += row[t]       * s_alpha[j][h0];
            acc1 += row[t + 128] * s_alpha[j][h1];
        }
        __syncthreads();
    }
    float o0 = acc0 + b1[t];       o0 = o0 > 0.f ? o0 : expf(o0) - 1.f;
    float o1 = acc1 + b1[t + 128]; o1 = o1 > 0.f ? o1 : expf(o1) - 1.f;
    g_h[n * 256 + t] = o0;
    g_h[n * 256 + t + 128] = o1;
}

// ---------------- GEMM2 (h @ W2) fused with el2/er2 reduction ----------------
__global__ void __launch_bounds__(256) k_gemm2(const float* __restrict__ W2,
                                               const float* __restrict__ al2,
                                               const float* __restrict__ ar2) {
    __shared__ float Ws[4096];
    __shared__ float Hs[4096];
    int tid = threadIdx.x;
    int nb0 = blockIdx.x * 16;

    const float4* w4 = (const float4*)W2;
    float4* ws4 = (float4*)Ws;
    const float4* h4 = (const float4*)(g_h + nb0 * 256);
    float4* hs4 = (float4*)Hs;
    for (int i = tid; i < 1024; i += 256) { ws4[i] = w4[i]; hs4[i] = h4[i]; }
    __syncthreads();

    int r = tid >> 4, c = tid & 15;
    const float* hr = Hs + r * 256;
    float acc = 0.f;
    #pragma unroll 8
    for (int k = 0; k < 256; k++) acc += hr[k] * Ws[k * 16 + c];

    int node = nb0 + r;
    g_feat2[node * 16 + c] = acc;

    float vl = acc * al2[c];
    float vr = acc * ar2[c];
    #pragma unroll
    for (int o = 8; o; o >>= 1) {
        vl += __shfl_xor_sync(0xffffffffu, vl, o);
        vr += __shfl_xor_sync(0xffffffffu, vr, o);
    }
    if (c == 0) { g_el2[node] = vl; g_er2[node] = vr; }
}

// ---------------- layer-2 fused edge-softmax + aggregate + bias (warp/node) ----------------
__global__ void __launch_bounds__(256) k_aggr2(const float* __restrict__ b2,
                                               float* __restrict__ out) {
    int n = (blockIdx.x * blockDim.x + threadIdx.x) >> 5;
    int lane = threadIdx.x & 31;
    if (n >= NN) return;
    int beg = g_off[n], deg = g_off[n + 1] - beg;

    if (deg == 0) {
        if (lane < 16) out[n * 16 + lane] = b2[lane];
        return;
    }
    float ern = g_er2[n];
    float m = -1e30f;
    for (int i = lane; i < deg; i += 32) {
        int s = g_col[beg + i];
        float e = g_el2[s] + ern; e = e > 0.f ? e : 0.2f * e;
        m = fmaxf(m, e);
    }
    #pragma unroll
    for (int o = 16; o; o >>= 1) m = fmaxf(m, __shfl_xor_sync(0xffffffffu, m, o));
    float den = 0.f;
    for (int i = lane; i < deg; i += 32) {
        int s = g_col[beg + i];
        float e = g_el2[s] + ern; e = e > 0.f ? e : 0.2f * e;
        den += expf(e - m);
    }
    #pragma unroll
    for (int o = 16; o; o >>= 1) den += __shfl_xor_sync(0xffffffffu, den, o);
    float inv = 1.f / den;

    int f = lane & 15, half = lane >> 4;
    float acc = 0.f;
    for (int i = half; i < deg; i += 2) {
        int s = g_col[beg + i];
        float e = g_el2[s] + ern; e = e > 0.f ? e : 0.2f * e;
        float a = expf(e - m) * inv;
        acc += g_feat2[s * 16 + f] * a;
    }
    acc += __shfl_xor_sync(0xffffffffu, acc, 16);
    if (lane < 16) out[n * 16 + lane] = acc + b2[lane];
}

// ---------------- log_softmax over 16 classes (16 lanes per node) ----------------
__global__ void k_logsm(float* __restrict__ out) {
    int idx = blockIdx.x * 256 + threadIdx.x;   // grid sized exactly N*16
    float v = out[idx];
    float m = v;
    #pragma unroll
    for (int o = 8; o; o >>= 1) m = fmaxf(m, __shfl_xor_sync(0xffffffffu, m, o));
    float s = expf(v - m);
    #pragma unroll
    for (int o = 8; o; o >>= 1) s += __shfl_xor_sync(0xffffffffu, s, o);
    out[idx] = v - (m + logf(s));
}

// ---------------- launch ----------------
extern "C" void kernel_launch(void* const* d_in, const int* in_sizes, int n_in,
                              void* d_out, int out_size) {
    const float* x   = (const float*)d_in[0];
    const int*   src = (const int*)d_in[1];
    const int*   dst = (const int*)d_in[2];
    const float* W1  = (const float*)d_in[3];
    const float* al1 = (const float*)d_in[4];
    const float* ar1 = (const float*)d_in[5];
    const float* b1  = (const float*)d_in[6];
    const float* W2  = (const float*)d_in[7];
    const float* al2 = (const float*)d_in[8];
    const float* ar2 = (const float*)d_in[9];
    const float* b2  = (const float*)d_in[10];
    float* out = (float*)d_out;

    // CSR build (dst-sorted)
    k_clear<<<(NN + 255) / 256, 256>>>();
    k_hist<<<(EE + 255) / 256, 256>>>(dst);
    k_scan<<<1, 1024>>>();
    k_scatter<<<(EE + 255) / 256, 256>>>(src, dst);

    // layer 1
    k_gemm1<<<dim3(256 / 64, (NN + 63) / 64), 128>>>(x, W1);
    k_el1<<<(NN * NH + 255) / 256, 256>>>(al1, ar1);
    k_aggr1<<<NN, 128>>>(b1);

    // layer 2
    k_gemm2<<<NN / 16, 256>>>(W2, al2, ar2);
    k_aggr2<<<(NN * 32 + 255) / 256, 256>>>(b2, out);
    k_logsm<<<(NN * 16) / 256, 256>>>(out);
}

// round 11
// speedup vs baseline: 1.2224x; 1.2224x over previous
#include <cuda_runtime.h>
#include <cuda_bf16.h>
#include <mma.h>
#include <math.h>
#include <stdint.h>

using namespace nvcuda;

#define NN 50000
#define NPAD 50048              // 391 * 128, padded M for unguarded wmma stores
#define EE 800000
#define NF 256
#define NH 4
#define ND 64
#define NC 16

// ---------------- device scratch (static, no allocation) ----------------
__device__ float g_feat1[NPAD * NF];    // x @ W1          [Npad,256]
__device__ float g_h[NN * NF];          // elu(aggr1+b1)   [N,256]
__device__ float g_feat2[NN * NC];      // h @ W2          [N,16]
__device__ float g_el1[NN * NH];
__device__ float g_er1[NN * NH];
__device__ float g_el2[NN];
__device__ float g_er2[NN];
__device__ int   g_deg[NN];
__device__ int   g_cur[NN];
__device__ int   g_off[NN + 1];
__device__ int   g_col[EE];             // src node per CSR slot (sorted by dst)

// bf16 split operands for tensor-core GEMM1
__device__ __nv_bfloat16 g_xh[NN * NF];
__device__ __nv_bfloat16 g_xl[NN * NF];
__device__ __nv_bfloat16 g_wh[NF * NF];   // W1^T hi  [n][k]
__device__ __nv_bfloat16 g_wl[NF * NF];   // W1^T lo  [n][k]

// ---------------- CSR build ----------------
__global__ void k_clear() {
    int i = blockIdx.x * blockDim.x + threadIdx.x;
    if (i < NN) { g_deg[i] = 0; g_cur[i] = 0; }
}

__global__ void k_hist(const int* __restrict__ dst) {
    int e = blockIdx.x * blockDim.x + threadIdx.x;
    if (e < EE) atomicAdd(&g_deg[dst[e]], 1);
}

__global__ void k_scan() {
    __shared__ int warpsum[32];
    __shared__ int carry_s;
    int t = threadIdx.x, lane = t & 31, wid = t >> 5;
    if (t == 0) carry_s = 0;
    __syncthreads();
    for (int base = 0; base < NN; base += 1024) {
        int i = base + t;
        int v = (i < NN) ? g_deg[i] : 0;
        int x = v;
        #pragma unroll
        for (int o = 1; o < 32; o <<= 1) {
            int y = __shfl_up_sync(0xffffffffu, x, o);
            if (lane >= o) x += y;
        }
        if (lane == 31) warpsum[wid] = x;
        __syncthreads();
        if (wid == 0) {
            int w = warpsum[lane];
            #pragma unroll
            for (int o = 1; o < 32; o <<= 1) {
                int y = __shfl_up_sync(0xffffffffu, w, o);
                if (lane >= o) w += y;
            }
            warpsum[lane] = w;
        }
        __syncthreads();
        int pre  = (wid > 0) ? warpsum[wid - 1] : 0;
        int incl = x + pre;
        if (i < NN) g_off[i] = carry_s + incl - v;
        int total = warpsum[31];
        __syncthreads();
        if (t == 0) carry_s += total;
        __syncthreads();
    }
    if (threadIdx.x == 0) g_off[NN] = carry_s;
}

__global__ void k_scatter(const int* __restrict__ src, const int* __restrict__ dst) {
    int e = blockIdx.x * blockDim.x + threadIdx.x;
    if (e < EE) {
        int d = dst[e];
        int p = g_off[d] + atomicAdd(&g_cur[d], 1);
        g_col[p] = src[e];
    }
}

// ---------------- bf16 split conversions ----------------
__global__ void k_cvt_x(const float* __restrict__ x) {
    int i = blockIdx.x * 256 + threadIdx.x;           // grid sized exactly NN*256/256
    float v = x[i];
    __nv_bfloat16 h = __float2bfloat16(v);
    float r = v - __bfloat162float(h);
    g_xh[i] = h;
    g_xl[i] = __float2bfloat16(r);
}

__global__ void k_cvt_w(const float* __restrict__ W1) {
    int i = blockIdx.x * 256 + threadIdx.x;           // 256 blocks -> 65536 = 256*256
    int n = i >> 8, k = i & 255;
    float v = W1[k * 256 + n];                        // transpose: W1T[n][k] = W1[k][n]
    __nv_bfloat16 h = __float2bfloat16(v);
    float r = v - __bfloat162float(h);
    g_wh[n * 256 + k] = h;
    g_wl[n * 256 + k] = __float2bfloat16(r);
}

// ---------------- GEMM1 via mma.sync (wmma bf16, split 3-term) -----------------
// feat1 = x @ W1, fp32-equivalent precision via (Ah+Al)(Bh+Bl) ~= AhBh+AhBl+AlBh
#define BM 128
#define BN 128
#define BK 32
#define LDS 48                                  // padded k-stride (elements), 96B
#define OFF_AH 0
#define OFF_AL (BM * LDS)
#define OFF_BH (2 * BM * LDS)
#define OFF_BL (3 * BM * LDS)
#define G1_SMEM (4 * BM * LDS * 2)              // 49152 bytes

__global__ void __launch_bounds__(256) k_gemm1_mma() {
    extern __shared__ __nv_bfloat16 smem[];
    const int tid = threadIdx.x;
    const int warp = tid >> 5;
    const int wm = warp & 3;                    // 4 warps along M (32 rows each)
    const int wn = warp >> 2;                   // 2 warps along N (64 cols each)
    const int m0 = blockIdx.y * BM;
    const int n0 = blockIdx.x * BN;

    wmma::fragment<wmma::accumulator, 16, 16, 16, float> acc[2][4];
    #pragma unroll
    for (int i = 0; i < 2; i++)
        #pragma unroll
        for (int j = 0; j < 4; j++) wmma::fill_fragment(acc[i][j], 0.0f);

    for (int kt = 0; kt < NF; kt += BK) {
        // fill A tiles (hi/lo): 128 rows x 32 k, 512 uint4 per matrix
        #pragma unroll
        for (int r = 0; r < 2; r++) {
            int idx = tid + r * 256;
            int row = idx >> 2;
            int col = (idx & 3) * 8;
            int g = m0 + row;
            uint4 vh = make_uint4(0, 0, 0, 0), vl = make_uint4(0, 0, 0, 0);
            if (g < NN) {
                const __nv_bfloat16* ph = g_xh + g * NF + kt + col;
                const __nv_bfloat16* pl = g_xl + g * NF + kt + col;
                vh = *(const uint4*)ph;
                vl = *(const uint4*)pl;
            }
            *(uint4*)(smem + OFF_AH + row * LDS + col) = vh;
            *(uint4*)(smem + OFF_AL + row * LDS + col) = vl;
        }
        // fill B tiles (hi/lo): 128 n-rows x 32 k  (W1T is [n][k])
        #pragma unroll
        for (int r = 0; r < 2; r++) {
            int idx = tid + r * 256;
            int row = idx >> 2;
            int col = (idx & 3) * 8;
            int g = (n0 + row) * NF + kt + col;
            *(uint4*)(smem + OFF_BH + row * LDS + col) = *(const uint4*)(g_wh + g);
            *(uint4*)(smem + OFF_BL + row * LDS + col) = *(const uint4*)(g_wl + g);
        }
        __syncthreads();

        #pragma unroll
        for (int kk = 0; kk < BK; kk += 16) {
            wmma::fragment<wmma::matrix_a, 16, 16, 16, __nv_bfloat16, wmma::row_major> ah[2], al[2];
            wmma::fragment<wmma::matrix_b, 16, 16, 16, __nv_bfloat16, wmma::col_major> bh[4], bl[4];
            #pragma unroll
            for (int i = 0; i < 2; i++) {
                const __nv_bfloat16* p = smem + (wm * 32 + i * 16) * LDS + kk;
                wmma::load_matrix_sync(ah[i], p + OFF_AH, LDS);
                wmma::load_matrix_sync(al[i], p + OFF_AL, LDS);
            }
            #pragma unroll
            for (int j = 0; j < 4; j++) {
                const __nv_bfloat16* p = smem + (wn * 64 + j * 16) * LDS + kk;
                wmma::load_matrix_sync(bh[j], p + OFF_BH, LDS);
                wmma::load_matrix_sync(bl[j], p + OFF_BL, LDS);
            }
            #pragma unroll
            for (int i = 0; i < 2; i++)
                #pragma unroll
                for (int j = 0; j < 4; j++) {
                    wmma::mma_sync(acc[i][j], ah[i], bh[j], acc[i][j]);
                    wmma::mma_sync(acc[i][j], ah[i], bl[j], acc[i][j]);
                    wmma::mma_sync(acc[i][j], al[i], bh[j], acc[i][j]);
                }
        }
        __syncthreads();
    }

    // epilogue: rows beyond NN land in the padded region of g_feat1 (harmless)
    #pragma unroll
    for (int i = 0; i < 2; i++)
        #pragma unroll
        for (int j = 0; j < 4; j++) {
            float* p = g_feat1 + (size_t)(m0 + wm * 32 + i * 16) * NF + n0 + wn * 64 + j * 16;
            wmma::store_matrix_sync(p, acc[i][j], NF, wmma::mem_row_major);
        }
}

// ---------------- per-node attention scalars (layer 1) ----------------
__global__ void k_el1(const float* __restrict__ al1, const float* __restrict__ ar1) {
    int idx = blockIdx.x * blockDim.x + threadIdx.x;
    if (idx >= NN * NH) return;
    int n = idx >> 2, h = idx & 3;
    const float4* f = (const float4*)(g_feat1 + n * 256 + h * 64);
    const float4* a = (const float4*)(al1 + h * 64);
    const float4* r = (const float4*)(ar1 + h * 64);
    float sl = 0.f, sr = 0.f;
    #pragma unroll
    for (int i = 0; i < 16; i++) {
        float4 v = f[i], A = a[i], R = r[i];
        sl += v.x * A.x + v.y * A.y + v.z * A.z + v.w * A.w;
        sr += v.x * R.x + v.y * R.y + v.z * R.z + v.w * R.w;
    }
    g_el1[idx] = sl;
    g_er1[idx] = sr;
}

// ---------------- layer-1 fused edge-softmax + aggregate + bias + ELU ----------------
__global__ void __launch_bounds__(128) k_aggr1(const float* __restrict__ b1) {
    int n = blockIdx.x;
    int t = threadIdx.x;
    int beg = g_off[n], deg = g_off[n + 1] - beg;

    __shared__ float s_max[4], s_inv[4];
    __shared__ float s_alpha[128][4];
    __shared__ int   s_src[128];

    if (deg == 0) {
        float o0 = b1[t];       o0 = o0 > 0.f ? o0 : expf(o0) - 1.f;
        float o1 = b1[t + 128]; o1 = o1 > 0.f ? o1 : expf(o1) - 1.f;
        g_h[n * 256 + t] = o0;
        g_h[n * 256 + t + 128] = o1;
        return;
    }

    float4 ern = *(const float4*)(g_er1 + n * 4);

    if (t < 32) {
        float m0 = -1e30f, m1 = -1e30f, m2 = -1e30f, m3 = -1e30f;
        for (int i = t; i < deg; i += 32) {
            int s = g_col[beg + i];
            float4 el = *(const float4*)(g_el1 + s * 4);
            float e0 = el.x + ern.x; e0 = e0 > 0.f ? e0 : 0.2f * e0;
            float e1 = el.y + ern.y; e1 = e1 > 0.f ? e1 : 0.2f * e1;
            float e2 = el.z + ern.z; e2 = e2 > 0.f ? e2 : 0.2f * e2;
            float e3 = el.w + ern.w; e3 = e3 > 0.f ? e3 : 0.2f * e3;
            m0 = fmaxf(m0, e0); m1 = fmaxf(m1, e1);
            m2 = fmaxf(m2, e2); m3 = fmaxf(m3, e3);
        }
        #pragma unroll
        for (int o = 16; o; o >>= 1) {
            m0 = fmaxf(m0, __shfl_xor_sync(0xffffffffu, m0, o));
            m1 = fmaxf(m1, __shfl_xor_sync(0xffffffffu, m1, o));
            m2 = fmaxf(m2, __shfl_xor_sync(0xffffffffu, m2, o));
            m3 = fmaxf(m3, __shfl_xor_sync(0xffffffffu, m3, o));
        }
        float d0 = 0.f, d1 = 0.f, d2 = 0.f, d3 = 0.f;
        for (int i = t; i < deg; i += 32) {
            int s = g_col[beg + i];
            float4 el = *(const float4*)(g_el1 + s * 4);
            float e0 = el.x + ern.x; e0 = e0 > 0.f ? e0 : 0.2f * e0;
            float e1 = el.y + ern.y; e1 = e1 > 0.f ? e1 : 0.2f * e1;
            float e2 = el.z + ern.z; e2 = e2 > 0.f ? e2 : 0.2f * e2;
            float e3 = el.w + ern.w; e3 = e3 > 0.f ? e3 : 0.2f * e3;
            d0 += expf(e0 - m0); d1 += expf(e1 - m1);
            d2 += expf(e2 - m2); d3 += expf(e3 - m3);
        }
        #pragma unroll
        for (int o = 16; o; o >>= 1) {
            d0 += __shfl_xor_sync(0xffffffffu, d0, o);
            d1 += __shfl_xor_sync(0xffffffffu, d1, o);
            d2 += __shfl_xor_sync(0xffffffffu, d2, o);
            d3 += __shfl_xor_sync(0xffffffffu, d3, o);
        }
        if (t == 0) {
            s_max[0] = m0; s_max[1] = m1; s_max[2] = m2; s_max[3] = m3;
            s_inv[0] = 1.f / d0; s_inv[1] = 1.f / d1;
            s_inv[2] = 1.f / d2; s_inv[3] = 1.f / d3;
        }
    }
    __syncthreads();

    float acc0 = 0.f, acc1 = 0.f;
    int h0 = t >> 6;        // 0 or 1
    int h1 = h0 + 2;        // 2 or 3

    for (int base = 0; base < deg; base += 128) {
        int i = base + t;
        if (i < deg) {
            int s = g_col[beg + i];
            s_src[t] = s;
            float4 el = *(const float4*)(g_el1 + s * 4);
            float e0 = el.x + ern.x; e0 = e0 > 0.f ? e0 : 0.2f * e0;
            float e1 = el.y + ern.y; e1 = e1 > 0.f ? e1 : 0.2f * e1;
            float e2 = el.z + ern.z; e2 = e2 > 0.f ? e2 : 0.2f * e2;
            float e3 = el.w + ern.w; e3 = e3 > 0.f ? e3 : 0.2f * e3;
            s_alpha[t][0] = expf(e0 - s_max[0]) * s_inv[0];
            s_alpha[t][1] = expf(e1 - s_max[1]) * s_inv[1];
            s_alpha[t][2] = expf(e2 - s_max[2]) * s_inv[2];
            s_alpha[t][3] = expf(e3 - s_max[3]) * s_inv[3];
        }
        __syncthreads();
        int cnt = min(128, deg - base);
        #pragma unroll 4
        for (int j = 0; j < cnt; j++) {
            const float* row = g_feat1 + s_src[j] * 256;
            acc0 += row[t]       * s_alpha[j][h0];
            acc1 += row[t + 128] * s_alpha[j][h1];
        }
        __syncthreads();
    }
    float o0 = acc0 + b1[t];       o0 = o0 > 0.f ? o0 : expf(o0) - 1.f;
    float o1 = acc1 + b1[t + 128]; o1 = o1 > 0.f ? o1 : expf(o1) - 1.f;
    g_h[n * 256 + t] = o0;
    g_h[n * 256 + t + 128] = o1;
}

// ---------------- GEMM2 (h @ W2) fused with el2/er2 reduction ----------------
__global__ void __launch_bounds__(256) k_gemm2(const float* __restrict__ W2,
                                               const float* __restrict__ al2,
                                               const float* __restrict__ ar2) {
    __shared__ float Ws[4096];
    __shared__ float Hs[4096];
    int tid = threadIdx.x;
    int nb0 = blockIdx.x * 16;

    const float4* w4 = (const float4*)W2;
    float4* ws4 = (float4*)Ws;
    const float4* h4 = (const float4*)(g_h + nb0 * 256);
    float4* hs4 = (float4*)Hs;
    for (int i = tid; i < 1024; i += 256) { ws4[i] = w4[i]; hs4[i] = h4[i]; }
    __syncthreads();

    int r = tid >> 4, c = tid & 15;
    const float* hr = Hs + r * 256;
    float acc = 0.f;
    #pragma unroll 8
    for (int k = 0; k < 256; k++) acc += hr[k] * Ws[k * 16 + c];

    int node = nb0 + r;
    g_feat2[node * 16 + c] = acc;

    float vl = acc * al2[c];
    float vr = acc * ar2[c];
    #pragma unroll
    for (int o = 8; o; o >>= 1) {
        vl += __shfl_xor_sync(0xffffffffu, vl, o);
        vr += __shfl_xor_sync(0xffffffffu, vr, o);
    }
    if (c == 0) { g_el2[node] = vl; g_er2[node] = vr; }
}

// ---------------- layer-2 fused edge-softmax + aggregate + bias (warp/node) ----------------
__global__ void __launch_bounds__(256) k_aggr2(const float* __restrict__ b2,
                                               float* __restrict__ out) {
    int n = (blockIdx.x * blockDim.x + threadIdx.x) >> 5;
    int lane = threadIdx.x & 31;
    if (n >= NN) return;
    int beg = g_off[n], deg = g_off[n + 1] - beg;

    if (deg == 0) {
        if (lane < 16) out[n * 16 + lane] = b2[lane];
        return;
    }
    float ern = g_er2[n];
    float m = -1e30f;
    for (int i = lane; i < deg; i += 32) {
        int s = g_col[beg + i];
        float e = g_el2[s] + ern; e = e > 0.f ? e : 0.2f * e;
        m = fmaxf(m, e);
    }
    #pragma unroll
    for (int o = 16; o; o >>= 1) m = fmaxf(m, __shfl_xor_sync(0xffffffffu, m, o));
    float den = 0.f;
    for (int i = lane; i < deg; i += 32) {
        int s = g_col[beg + i];
        float e = g_el2[s] + ern; e = e > 0.f ? e : 0.2f * e;
        den += expf(e - m);
    }
    #pragma unroll
    for (int o = 16; o; o >>= 1) den += __shfl_xor_sync(0xffffffffu, den, o);
    float inv = 1.f / den;

    int f = lane & 15, half = lane >> 4;
    float acc = 0.f;
    for (int i = half; i < deg; i += 2) {
        int s = g_col[beg + i];
        float e = g_el2[s] + ern; e = e > 0.f ? e : 0.2f * e;
        float a = expf(e - m) * inv;
        acc += g_feat2[s * 16 + f] * a;
    }
    acc += __shfl_xor_sync(0xffffffffu, acc, 16);
    if (lane < 16) out[n * 16 + lane] = acc + b2[lane];
}

// ---------------- log_softmax over 16 classes ----------------
__global__ void k_logsm(float* __restrict__ out) {
    int idx = blockIdx.x * 256 + threadIdx.x;   // grid sized exactly N*16
    float v = out[idx];
    float m = v;
    #pragma unroll
    for (int o = 8; o; o >>= 1) m = fmaxf(m, __shfl_xor_sync(0xffffffffu, m, o));
    float s = expf(v - m);
    #pragma unroll
    for (int o = 8; o; o >>= 1) s += __shfl_xor_sync(0xffffffffu, s, o);
    out[idx] = v - (m + logf(s));
}

// ---------------- launch ----------------
extern "C" void kernel_launch(void* const* d_in, const int* in_sizes, int n_in,
                              void* d_out, int out_size) {
    const float* x   = (const float*)d_in[0];
    const int*   src = (const int*)d_in[1];
    const int*   dst = (const int*)d_in[2];
    const float* W1  = (const float*)d_in[3];
    const float* al1 = (const float*)d_in[4];
    const float* ar1 = (const float*)d_in[5];
    const float* b1  = (const float*)d_in[6];
    const float* W2  = (const float*)d_in[7];
    const float* al2 = (const float*)d_in[8];
    const float* ar2 = (const float*)d_in[9];
    const float* b2  = (const float*)d_in[10];
    float* out = (float*)d_out;

    // CSR build (dst-sorted)
    k_clear<<<(NN + 255) / 256, 256>>>();
    k_hist<<<(EE + 255) / 256, 256>>>(dst);
    k_scan<<<1, 1024>>>();
    k_scatter<<<(EE + 255) / 256, 256>>>(src, dst);

    // bf16 split conversion
    k_cvt_x<<<(NN * NF) / 256, 256>>>(x);
    k_cvt_w<<<(NF * NF) / 256, 256>>>(W1);

    // layer 1
    k_gemm1_mma<<<dim3(NF / BN, NPAD / BM), 256, G1_SMEM>>>();
    k_el1<<<(NN * NH + 255) / 256, 256>>>(al1, ar1);
    k_aggr1<<<NN, 128>>>(b1);

    // layer 2
    k_gemm2<<<NN / 16, 256>>>(W2, al2, ar2);
    k_aggr2<<<(NN * 32 + 255) / 256, 256>>>(b2, out);
    k_logsm<<<(NN * 16) / 256, 256>>>(out);
}

// round 12
// speedup vs baseline: 1.4404x; 1.1783x over previous
#include <cuda_runtime.h>
#include <cuda_bf16.h>
#include <mma.h>
#include <math.h>
#include <stdint.h>

using namespace nvcuda;

#define NN 50000
#define NPAD 50048              // 391 * 128, padded M for unguarded wmma stores
#define EE 800000
#define NF 256
#define NH 4
#define ND 64
#define NC 16

// ---------------- device scratch (static, no allocation) ----------------
__device__ float g_feat1[NPAD * NF];    // x @ W1          [Npad,256]
__device__ float g_h[NN * NF];          // elu(aggr1+b1)   [N,256]
__device__ float g_feat2[NN * NC];      // h @ W2          [N,16]
__device__ float g_el1[NN * NH];
__device__ float g_er1[NN * NH];
__device__ float g_el2[NN];
__device__ float g_er2[NN];
__device__ int   g_deg[NN];
__device__ int   g_cur[NN];
__device__ int   g_off[NN + 1];
__device__ int   g_col[EE];             // src node per CSR slot (sorted by dst)

// bf16 split operands for tensor-core GEMM1
__device__ __nv_bfloat16 g_xh[NN * NF];
__device__ __nv_bfloat16 g_xl[NN * NF];
__device__ __nv_bfloat16 g_wh[NF * NF];   // W1^T hi  [n][k]
__device__ __nv_bfloat16 g_wl[NF * NF];   // W1^T lo  [n][k]

// ---------------- CSR build ----------------
__global__ void k_clear() {
    int i = blockIdx.x * blockDim.x + threadIdx.x;
    if (i < NN) { g_deg[i] = 0; g_cur[i] = 0; }
}

__global__ void k_hist(const int* __restrict__ dst) {
    int e = blockIdx.x * blockDim.x + threadIdx.x;
    if (e < EE) atomicAdd(&g_deg[dst[e]], 1);
}

__global__ void k_scan() {
    __shared__ int warpsum[32];
    __shared__ int carry_s;
    int t = threadIdx.x, lane = t & 31, wid = t >> 5;
    if (t == 0) carry_s = 0;
    __syncthreads();
    for (int base = 0; base < NN; base += 1024) {
        int i = base + t;
        int v = (i < NN) ? g_deg[i] : 0;
        int x = v;
        #pragma unroll
        for (int o = 1; o < 32; o <<= 1) {
            int y = __shfl_up_sync(0xffffffffu, x, o);
            if (lane >= o) x += y;
        }
        if (lane == 31) warpsum[wid] = x;
        __syncthreads();
        if (wid == 0) {
            int w = warpsum[lane];
            #pragma unroll
            for (int o = 1; o < 32; o <<= 1) {
                int y = __shfl_up_sync(0xffffffffu, w, o);
                if (lane >= o) w += y;
            }
            warpsum[lane] = w;
        }
        __syncthreads();
        int pre  = (wid > 0) ? warpsum[wid - 1] : 0;
        int incl = x + pre;
        if (i < NN) g_off[i] = carry_s + incl - v;
        int total = warpsum[31];
        __syncthreads();
        if (t == 0) carry_s += total;
        __syncthreads();
    }
    if (threadIdx.x == 0) g_off[NN] = carry_s;
}

__global__ void k_scatter(const int* __restrict__ src, const int* __restrict__ dst) {
    int e = blockIdx.x * blockDim.x + threadIdx.x;
    if (e < EE) {
        int d = dst[e];
        int p = g_off[d] + atomicAdd(&g_cur[d], 1);
        g_col[p] = src[e];
    }
}

// ---------------- bf16 split conversions ----------------
__global__ void k_cvt_x(const float* __restrict__ x) {
    int i = blockIdx.x * 256 + threadIdx.x;           // grid sized exactly NN*256/256
    float v = x[i];
    __nv_bfloat16 h = __float2bfloat16(v);
    float r = v - __bfloat162float(h);
    g_xh[i] = h;
    g_xl[i] = __float2bfloat16(r);
}

__global__ void k_cvt_w(const float* __restrict__ W1) {
    int i = blockIdx.x * 256 + threadIdx.x;           // 256 blocks -> 65536 = 256*256
    int n = i >> 8, k = i & 255;
    float v = W1[k * 256 + n];                        // transpose: W1T[n][k] = W1[k][n]
    __nv_bfloat16 h = __float2bfloat16(v);
    float r = v - __bfloat162float(h);
    g_wh[n * 256 + k] = h;
    g_wl[n * 256 + k] = __float2bfloat16(r);
}

// ---------------- GEMM1 via mma.sync (wmma bf16, split 3-term) -----------------
// feat1 = x @ W1; 2-stage cp.async pipeline; LDS=56 => conflict-free smem rows.
#define BM 128
#define BN 128
#define BK 32
#define LDS 56
#define MAT_E (BM * LDS)                // 7168 elements per matrix tile
#define MAT_B (MAT_E * 2)               // 14336 bytes
#define STG_E (4 * MAT_E)               // 28672 elements per stage
#define STG_B (4 * MAT_B)               // 57344 bytes per stage
#define G1_SMEM (2 * STG_B)             // 114688 bytes

__device__ __forceinline__ void cp16(uint32_t dst, const void* src, int bytes) {
    asm volatile("cp.async.cg.shared.global [%0], [%1], 16, %2;\n"
                 :: "r"(dst), "l"(src), "r"(bytes));
}

__device__ __forceinline__ void g1_fill(uint32_t sb, int tid, int m0, int n0,
                                        int stage, int kt) {
    uint32_t base = sb + stage * STG_B;
    #pragma unroll
    for (int r = 0; r < 2; r++) {
        int idx = tid + r * 256;        // 0..511
        int row = idx >> 2;             // 0..127
        int col = (idx & 3) * 8;        // 0,8,16,24
        uint32_t so = (uint32_t)(row * LDS + col) * 2;
        int gA = m0 + row;
        int ok = (gA < NN) ? 16 : 0;
        int gAc = (gA < NN) ? gA : (NN - 1);
        cp16(base + so,             g_xh + (size_t)gAc * NF + kt + col, ok);
        cp16(base + MAT_B + so,     g_xl + (size_t)gAc * NF + kt + col, ok);
        cp16(base + 2 * MAT_B + so, g_wh + (size_t)(n0 + row) * NF + kt + col, 16);
        cp16(base + 3 * MAT_B + so, g_wl + (size_t)(n0 + row) * NF + kt + col, 16);
    }
}

__global__ void __launch_bounds__(256) k_gemm1_mma() {
    extern __shared__ __nv_bfloat16 smem[];
    uint32_t sb = (uint32_t)__cvta_generic_to_shared(smem);
    const int tid = threadIdx.x;
    const int warp = tid >> 5;
    const int wm = warp & 3;                    // 4 warps along M (32 rows each)
    const int wn = warp >> 2;                   // 2 warps along N (64 cols each)
    const int m0 = blockIdx.y * BM;
    const int n0 = blockIdx.x * BN;

    wmma::fragment<wmma::accumulator, 16, 16, 16, float> acc[2][4];
    #pragma unroll
    for (int i = 0; i < 2; i++)
        #pragma unroll
        for (int j = 0; j < 4; j++) wmma::fill_fragment(acc[i][j], 0.0f);

    g1_fill(sb, tid, m0, n0, 0, 0);
    asm volatile("cp.async.commit_group;\n");

    #pragma unroll 1
    for (int kt = 0; kt < NF / BK; kt++) {
        if (kt + 1 < NF / BK) {
            g1_fill(sb, tid, m0, n0, (kt + 1) & 1, (kt + 1) * BK);
            asm volatile("cp.async.commit_group;\n");
            asm volatile("cp.async.wait_group 1;\n");
        } else {
            asm volatile("cp.async.wait_group 0;\n");
        }
        __syncthreads();

        const __nv_bfloat16* st = smem + (kt & 1) * STG_E;
        #pragma unroll
        for (int kk = 0; kk < BK; kk += 16) {
            wmma::fragment<wmma::matrix_a, 16, 16, 16, __nv_bfloat16, wmma::row_major> ah[2], al[2];
            wmma::fragment<wmma::matrix_b, 16, 16, 16, __nv_bfloat16, wmma::col_major> bh[4], bl[4];
            #pragma unroll
            for (int i = 0; i < 2; i++) {
                const __nv_bfloat16* p = st + (wm * 32 + i * 16) * LDS + kk;
                wmma::load_matrix_sync(ah[i], p, LDS);
                wmma::load_matrix_sync(al[i], p + MAT_E, LDS);
            }
            #pragma unroll
            for (int j = 0; j < 4; j++) {
                const __nv_bfloat16* p = st + 2 * MAT_E + (wn * 64 + j * 16) * LDS + kk;
                wmma::load_matrix_sync(bh[j], p, LDS);
                wmma::load_matrix_sync(bl[j], p + MAT_E, LDS);
            }
            #pragma unroll
            for (int i = 0; i < 2; i++)
                #pragma unroll
                for (int j = 0; j < 4; j++) {
                    wmma::mma_sync(acc[i][j], ah[i], bh[j], acc[i][j]);
                    wmma::mma_sync(acc[i][j], ah[i], bl[j], acc[i][j]);
                    wmma::mma_sync(acc[i][j], al[i], bh[j], acc[i][j]);
                }
        }
        __syncthreads();
    }

    // epilogue: rows beyond NN land in the padded region of g_feat1 (harmless)
    #pragma unroll
    for (int i = 0; i < 2; i++)
        #pragma unroll
        for (int j = 0; j < 4; j++) {
            float* p = g_feat1 + (size_t)(m0 + wm * 32 + i * 16) * NF + n0 + wn * 64 + j * 16;
            wmma::store_matrix_sync(p, acc[i][j], NF, wmma::mem_row_major);
        }
}

// ---------------- per-node attention scalars (layer 1) ----------------
__global__ void k_el1(const float* __restrict__ al1, const float* __restrict__ ar1) {
    int idx = blockIdx.x * blockDim.x + threadIdx.x;
    if (idx >= NN * NH) return;
    int n = idx >> 2, h = idx & 3;
    const float4* f = (const float4*)(g_feat1 + n * 256 + h * 64);
    const float4* a = (const float4*)(al1 + h * 64);
    const float4* r = (const float4*)(ar1 + h * 64);
    float sl = 0.f, sr = 0.f;
    #pragma unroll
    for (int i = 0; i < 16; i++) {
        float4 v = f[i], A = a[i], R = r[i];
        sl += v.x * A.x + v.y * A.y + v.z * A.z + v.w * A.w;
        sr += v.x * R.x + v.y * R.y + v.z * R.z + v.w * R.w;
    }
    g_el1[idx] = sl;
    g_er1[idx] = sr;
}

// ---------------- layer-1 fused softmax-aggregate (single pass, unnormalized) ------
// out = sum_j exp(e_j) feat_j / sum_j exp(e_j)  — max-subtraction dropped (e bounded),
// normalization deferred to a single divide at the end.
__global__ void __launch_bounds__(128) k_aggr1(const float* __restrict__ b1) {
    int n = blockIdx.x;
    int t = threadIdx.x;
    int beg = g_off[n], deg = g_off[n + 1] - beg;

    __shared__ float s_ex[128][4];
    __shared__ int   s_src[128];

    if (deg == 0) {
        float o0 = b1[t];       o0 = o0 > 0.f ? o0 : __expf(o0) - 1.f;
        float o1 = b1[t + 128]; o1 = o1 > 0.f ? o1 : __expf(o1) - 1.f;
        g_h[n * 256 + t] = o0;
        g_h[n * 256 + t + 128] = o1;
        return;
    }

    float4 ern = *(const float4*)(g_er1 + n * 4);

    float acc0 = 0.f, acc1 = 0.f, den0 = 0.f, den1 = 0.f;
    int h0 = t >> 6;        // 0 or 1 (uniform per warp)
    int h1 = h0 + 2;        // 2 or 3

    for (int base = 0; base < deg; base += 128) {
        int i = base + t;
        if (i < deg) {
            int s = g_col[beg + i];
            s_src[t] = s;
            float4 el = *(const float4*)(g_el1 + s * 4);
            float e0 = el.x + ern.x; e0 = e0 > 0.f ? e0 : 0.2f * e0;
            float e1 = el.y + ern.y; e1 = e1 > 0.f ? e1 : 0.2f * e1;
            float e2 = el.z + ern.z; e2 = e2 > 0.f ? e2 : 0.2f * e2;
            float e3 = el.w + ern.w; e3 = e3 > 0.f ? e3 : 0.2f * e3;
            s_ex[t][0] = __expf(e0);
            s_ex[t][1] = __expf(e1);
            s_ex[t][2] = __expf(e2);
            s_ex[t][3] = __expf(e3);
        }
        __syncthreads();
        int cnt = min(128, deg - base);
        #pragma unroll 4
        for (int j = 0; j < cnt; j++) {
            const float* row = g_feat1 + (size_t)s_src[j] * 256;
            float a0 = s_ex[j][h0];
            float a1 = s_ex[j][h1];
            den0 += a0; den1 += a1;
            acc0 += row[t]       * a0;
            acc1 += row[t + 128] * a1;
        }
        __syncthreads();
    }
    float o0 = acc0 / den0 + b1[t];       o0 = o0 > 0.f ? o0 : __expf(o0) - 1.f;
    float o1 = acc1 / den1 + b1[t + 128]; o1 = o1 > 0.f ? o1 : __expf(o1) - 1.f;
    g_h[n * 256 + t] = o0;
    g_h[n * 256 + t + 128] = o1;
}

// ---------------- GEMM2 (h @ W2) fused with el2/er2 reduction ----------------
__global__ void __launch_bounds__(256) k_gemm2(const float* __restrict__ W2,
                                               const float* __restrict__ al2,
                                               const float* __restrict__ ar2) {
    __shared__ float Ws[4096];
    __shared__ float Hs[4096];
    int tid = threadIdx.x;
    int nb0 = blockIdx.x * 16;

    const float4* w4 = (const float4*)W2;
    float4* ws4 = (float4*)Ws;
    const float4* h4 = (const float4*)(g_h + nb0 * 256);
    float4* hs4 = (float4*)Hs;
    for (int i = tid; i < 1024; i += 256) { ws4[i] = w4[i]; hs4[i] = h4[i]; }
    __syncthreads();

    int r = tid >> 4, c = tid & 15;
    const float* hr = Hs + r * 256;
    float acc = 0.f;
    #pragma unroll 8
    for (int k = 0; k < 256; k++) acc += hr[k] * Ws[k * 16 + c];

    int node = nb0 + r;
    g_feat2[node * 16 + c] = acc;

    float vl = acc * al2[c];
    float vr = acc * ar2[c];
    #pragma unroll
    for (int o = 8; o; o >>= 1) {
        vl += __shfl_xor_sync(0xffffffffu, vl, o);
        vr += __shfl_xor_sync(0xffffffffu, vr, o);
    }
    if (c == 0) { g_el2[node] = vl; g_er2[node] = vr; }
}

// ---------------- layer-2 fused softmax-aggregate (single pass, warp/node) --------
__global__ void __launch_bounds__(256) k_aggr2(const float* __restrict__ b2,
                                               float* __restrict__ out) {
    int n = (blockIdx.x * blockDim.x + threadIdx.x) >> 5;
    int lane = threadIdx.x & 31;
    if (n >= NN) return;
    int beg = g_off[n], deg = g_off[n + 1] - beg;

    if (deg == 0) {
        if (lane < 16) out[n * 16 + lane] = b2[lane];
        return;
    }
    float ern = g_er2[n];
    int f = lane & 15, half = lane >> 4;
    float acc = 0.f, den = 0.f;
    for (int i = half; i < deg; i += 2) {
        int s = g_col[beg + i];
        float e = g_el2[s] + ern; e = e > 0.f ? e : 0.2f * e;
        float a = __expf(e);
        den += a;
        acc += g_feat2[s * 16 + f] * a;
    }
    acc += __shfl_xor_sync(0xffffffffu, acc, 16);
    den += __shfl_xor_sync(0xffffffffu, den, 16);
    if (lane < 16) out[n * 16 + lane] = acc / den + b2[lane];
}

// ---------------- log_softmax over 16 classes ----------------
__global__ void k_logsm(float* __restrict__ out) {
    int idx = blockIdx.x * 256 + threadIdx.x;   // grid sized exactly N*16
    float v = out[idx];
    float m = v;
    #pragma unroll
    for (int o = 8; o; o >>= 1) m = fmaxf(m, __shfl_xor_sync(0xffffffffu, m, o));
    float s = expf(v - m);
    #pragma unroll
    for (int o = 8; o; o >>= 1) s += __shfl_xor_sync(0xffffffffu, s, o);
    out[idx] = v - (m + logf(s));
}

// ---------------- launch ----------------
extern "C" void kernel_launch(void* const* d_in, const int* in_sizes, int n_in,
                              void* d_out, int out_size) {
    const float* x   = (const float*)d_in[0];
    const int*   src = (const int*)d_in[1];
    const int*   dst = (const int*)d_in[2];
    const float* W1  = (const float*)d_in[3];
    const float* al1 = (const float*)d_in[4];
    const float* ar1 = (const float*)d_in[5];
    const float* b1  = (const float*)d_in[6];
    const float* W2  = (const float*)d_in[7];
    const float* al2 = (const float*)d_in[8];
    const float* ar2 = (const float*)d_in[9];
    const float* b2  = (const float*)d_in[10];
    float* out = (float*)d_out;

    static int smem_set = 0;
    if (!smem_set) {
        cudaFuncSetAttribute(k_gemm1_mma, cudaFuncAttributeMaxDynamicSharedMemorySize, G1_SMEM);
        smem_set = 1;
    }

    // CSR build (dst-sorted)
    k_clear<<<(NN + 255) / 256, 256>>>();
    k_hist<<<(EE + 255) / 256, 256>>>(dst);
    k_scan<<<1, 1024>>>();
    k_scatter<<<(EE + 255) / 256, 256>>>(src, dst);

    // bf16 split conversion
    k_cvt_x<<<(NN * NF) / 256, 256>>>(x);
    k_cvt_w<<<(NF * NF) / 256, 256>>>(W1);

    // layer 1
    k_gemm1_mma<<<dim3(NF / BN, NPAD / BM), 256, G1_SMEM>>>();
    k_el1<<<(NN * NH + 255) / 256, 256>>>(al1, ar1);
    k_aggr1<<<NN, 128>>>(b1);

    // layer 2
    k_gemm2<<<NN / 16, 256>>>(W2, al2, ar2);
    k_aggr2<<<(NN * 32 + 255) / 256, 256>>>(b2, out);
    k_logsm<<<(NN * 16) / 256, 256>>>(out);
}

// round 13
// speedup vs baseline: 1.8109x; 1.2572x over previous
#include <cuda_runtime.h>
#include <cuda_bf16.h>
#include <mma.h>
#include <math.h>
#include <stdint.h>

using namespace nvcuda;

#define NN 50000
#define NPAD 50048              // 391 * 128, padded M for unguarded wmma stores
#define EE 800000
#define NF 256
#define NH 4
#define ND 64
#define NC 16

// ---------------- device scratch (static, no allocation) ----------------
__device__ float g_feat1[NPAD * NF];    // x @ W1          [Npad,256]
__device__ float g_h[NN * NF];          // elu(aggr1+b1)   [N,256]
__device__ float g_feat2[NN * NC];      // h @ W2          [N,16]
__device__ float g_el1[NN * NH];
__device__ float g_er1[NN * NH];
__device__ float g_el2[NN];
__device__ float g_er2[NN];
__device__ int   g_deg[NN];
__device__ int   g_cur[NN];
__device__ int   g_off[NN + 1];
__device__ int   g_col[EE];             // src node per CSR slot (sorted by dst)

// bf16 split operands for tensor-core GEMM1
__device__ __nv_bfloat16 g_xh[NN * NF];
__device__ __nv_bfloat16 g_xl[NN * NF];
__device__ __nv_bfloat16 g_wh[NF * NF];   // W1^T hi  [n][k]
__device__ __nv_bfloat16 g_wl[NF * NF];   // W1^T lo  [n][k]

// ---------------- CSR build ----------------
__global__ void k_clear() {
    int i = blockIdx.x * blockDim.x + threadIdx.x;
    if (i < NN) { g_deg[i] = 0; g_cur[i] = 0; }
}

__global__ void k_hist(const int* __restrict__ dst) {
    int e = blockIdx.x * blockDim.x + threadIdx.x;
    if (e < EE) atomicAdd(&g_deg[dst[e]], 1);
}

__global__ void k_scan() {
    __shared__ int warpsum[32];
    __shared__ int carry_s;
    int t = threadIdx.x, lane = t & 31, wid = t >> 5;
    if (t == 0) carry_s = 0;
    __syncthreads();
    for (int base = 0; base < NN; base += 1024) {
        int i = base + t;
        int v = (i < NN) ? g_deg[i] : 0;
        int x = v;
        #pragma unroll
        for (int o = 1; o < 32; o <<= 1) {
            int y = __shfl_up_sync(0xffffffffu, x, o);
            if (lane >= o) x += y;
        }
        if (lane == 31) warpsum[wid] = x;
        __syncthreads();
        if (wid == 0) {
            int w = warpsum[lane];
            #pragma unroll
            for (int o = 1; o < 32; o <<= 1) {
                int y = __shfl_up_sync(0xffffffffu, w, o);
                if (lane >= o) w += y;
            }
            warpsum[lane] = w;
        }
        __syncthreads();
        int pre  = (wid > 0) ? warpsum[wid - 1] : 0;
        int incl = x + pre;
        if (i < NN) g_off[i] = carry_s + incl - v;
        int total = warpsum[31];
        __syncthreads();
        if (t == 0) carry_s += total;
        __syncthreads();
    }
    if (threadIdx.x == 0) g_off[NN] = carry_s;
}

__global__ void k_scatter(const int* __restrict__ src, const int* __restrict__ dst) {
    int e = blockIdx.x * blockDim.x + threadIdx.x;
    if (e < EE) {
        int d = dst[e];
        int p = g_off[d] + atomicAdd(&g_cur[d], 1);
        g_col[p] = src[e];
    }
}

// ---------------- bf16 split conversions ----------------
__global__ void k_cvt_x(const float* __restrict__ x) {
    int i = blockIdx.x * 256 + threadIdx.x;           // grid sized exactly NN*256/256
    float v = x[i];
    __nv_bfloat16 h = __float2bfloat16(v);
    float r = v - __bfloat162float(h);
    g_xh[i] = h;
    g_xl[i] = __float2bfloat16(r);
}

__global__ void k_cvt_w(const float* __restrict__ W1) {
    int i = blockIdx.x * 256 + threadIdx.x;           // 256 blocks -> 65536 = 256*256
    int n = i >> 8, k = i & 255;
    float v = W1[k * 256 + n];                        // transpose: W1T[n][k] = W1[k][n]
    __nv_bfloat16 h = __float2bfloat16(v);
    float r = v - __bfloat162float(h);
    g_wh[n * 256 + k] = h;
    g_wl[n * 256 + k] = __float2bfloat16(r);
}

// ---------------- GEMM1 via mma.sync (wmma bf16, split 3-term) -----------------
// feat1 = x @ W1; 2-stage cp.async pipeline; LDS=56 => conflict-free smem rows.
#define BM 128
#define BN 128
#define BK 32
#define LDS 56
#define MAT_E (BM * LDS)                // 7168 elements per matrix tile
#define MAT_B (MAT_E * 2)               // 14336 bytes
#define STG_E (4 * MAT_E)               // 28672 elements per stage
#define STG_B (4 * MAT_B)               // 57344 bytes per stage
#define G1_SMEM (2 * STG_B)             // 114688 bytes

__device__ __forceinline__ void cp16(uint32_t dst, const void* src, int bytes) {
    asm volatile("cp.async.cg.shared.global [%0], [%1], 16, %2;\n"
                 :: "r"(dst), "l"(src), "r"(bytes));
}

__device__ __forceinline__ void g1_fill(uint32_t sb, int tid, int m0, int n0,
                                        int stage, int kt) {
    uint32_t base = sb + stage * STG_B;
    #pragma unroll
    for (int r = 0; r < 2; r++) {
        int idx = tid + r * 256;        // 0..511
        int row = idx >> 2;             // 0..127
        int col = (idx & 3) * 8;        // 0,8,16,24
        uint32_t so = (uint32_t)(row * LDS + col) * 2;
        int gA = m0 + row;
        int ok = (gA < NN) ? 16 : 0;
        int gAc = (gA < NN) ? gA : (NN - 1);
        cp16(base + so,             g_xh + (size_t)gAc * NF + kt + col, ok);
        cp16(base + MAT_B + so,     g_xl + (size_t)gAc * NF + kt + col, ok);
        cp16(base + 2 * MAT_B + so, g_wh + (size_t)(n0 + row) * NF + kt + col, 16);
        cp16(base + 3 * MAT_B + so, g_wl + (size_t)(n0 + row) * NF + kt + col, 16);
    }
}

__global__ void __launch_bounds__(256) k_gemm1_mma() {
    extern __shared__ __nv_bfloat16 smem[];
    uint32_t sb = (uint32_t)__cvta_generic_to_shared(smem);
    const int tid = threadIdx.x;
    const int warp = tid >> 5;
    const int wm = warp & 3;                    // 4 warps along M (32 rows each)
    const int wn = warp >> 2;                   // 2 warps along N (64 cols each)
    const int m0 = blockIdx.y * BM;
    const int n0 = blockIdx.x * BN;

    wmma::fragment<wmma::accumulator, 16, 16, 16, float> acc[2][4];
    #pragma unroll
    for (int i = 0; i < 2; i++)
        #pragma unroll
        for (int j = 0; j < 4; j++) wmma::fill_fragment(acc[i][j], 0.0f);

    g1_fill(sb, tid, m0, n0, 0, 0);
    asm volatile("cp.async.commit_group;\n");

    #pragma unroll 1
    for (int kt = 0; kt < NF / BK; kt++) {
        if (kt + 1 < NF / BK) {
            g1_fill(sb, tid, m0, n0, (kt + 1) & 1, (kt + 1) * BK);
            asm volatile("cp.async.commit_group;\n");
            asm volatile("cp.async.wait_group 1;\n");
        } else {
            asm volatile("cp.async.wait_group 0;\n");
        }
        __syncthreads();

        const __nv_bfloat16* st = smem + (kt & 1) * STG_E;
        #pragma unroll
        for (int kk = 0; kk < BK; kk += 16) {
            wmma::fragment<wmma::matrix_a, 16, 16, 16, __nv_bfloat16, wmma::row_major> ah[2], al[2];
            wmma::fragment<wmma::matrix_b, 16, 16, 16, __nv_bfloat16, wmma::col_major> bh[4], bl[4];
            #pragma unroll
            for (int i = 0; i < 2; i++) {
                const __nv_bfloat16* p = st + (wm * 32 + i * 16) * LDS + kk;
                wmma::load_matrix_sync(ah[i], p, LDS);
                wmma::load_matrix_sync(al[i], p + MAT_E, LDS);
            }
            #pragma unroll
            for (int j = 0; j < 4; j++) {
                const __nv_bfloat16* p = st + 2 * MAT_E + (wn * 64 + j * 16) * LDS + kk;
                wmma::load_matrix_sync(bh[j], p, LDS);
                wmma::load_matrix_sync(bl[j], p + MAT_E, LDS);
            }
            #pragma unroll
            for (int i = 0; i < 2; i++)
                #pragma unroll
                for (int j = 0; j < 4; j++) {
                    wmma::mma_sync(acc[i][j], ah[i], bh[j], acc[i][j]);
                    wmma::mma_sync(acc[i][j], ah[i], bl[j], acc[i][j]);
                    wmma::mma_sync(acc[i][j], al[i], bh[j], acc[i][j]);
                }
        }
        __syncthreads();
    }

    // epilogue: rows beyond NN land in the padded region of g_feat1 (harmless)
    #pragma unroll
    for (int i = 0; i < 2; i++)
        #pragma unroll
        for (int j = 0; j < 4; j++) {
            float* p = g_feat1 + (size_t)(m0 + wm * 32 + i * 16) * NF + n0 + wn * 64 + j * 16;
            wmma::store_matrix_sync(p, acc[i][j], NF, wmma::mem_row_major);
        }
}

// ---------------- per-node attention scalars (layer 1) ----------------
__global__ void k_el1(const float* __restrict__ al1, const float* __restrict__ ar1) {
    int idx = blockIdx.x * blockDim.x + threadIdx.x;
    if (idx >= NN * NH) return;
    int n = idx >> 2, h = idx & 3;
    const float4* f = (const float4*)(g_feat1 + n * 256 + h * 64);
    const float4* a = (const float4*)(al1 + h * 64);
    const float4* r = (const float4*)(ar1 + h * 64);
    float sl = 0.f, sr = 0.f;
    #pragma unroll
    for (int i = 0; i < 16; i++) {
        float4 v = f[i], A = a[i], R = r[i];
        sl += v.x * A.x + v.y * A.y + v.z * A.z + v.w * A.w;
        sr += v.x * R.x + v.y * R.y + v.z * R.z + v.w * R.w;
    }
    g_el1[idx] = sl;
    g_er1[idx] = sr;
}

// ---------------- layer-1 fused softmax-aggregate (single pass, float4, 64 thr/node)
// out = sum_j exp(e_j) feat_j / sum_j exp(e_j); thread t owns float4 slot t
// (features 4t..4t+3, head = t>>4); one LDG.128 per edge-row per thread.
__global__ void __launch_bounds__(64) k_aggr1(const float* __restrict__ b1) {
    int n = blockIdx.x;
    int t = threadIdx.x;                 // 0..63
    int beg = g_off[n], deg = g_off[n + 1] - beg;

    __shared__ float s_ex[64][5];        // stride 5: conflict-free writes
    __shared__ int   s_src[64];

    float4 bb = ((const float4*)b1)[t];

    if (deg == 0) {
        float4 o;
        o.x = bb.x > 0.f ? bb.x : __expf(bb.x) - 1.f;
        o.y = bb.y > 0.f ? bb.y : __expf(bb.y) - 1.f;
        o.z = bb.z > 0.f ? bb.z : __expf(bb.z) - 1.f;
        o.w = bb.w > 0.f ? bb.w : __expf(bb.w) - 1.f;
        ((float4*)(g_h + n * 256))[t] = o;
        return;
    }

    float4 ern = *(const float4*)(g_er1 + n * 4);
    const int h = t >> 4;                // head for this thread's slot

    float4 acc = make_float4(0.f, 0.f, 0.f, 0.f);
    float den = 0.f;

    for (int base = 0; base < deg; base += 64) {
        int i = base + t;
        if (i < deg) {
            int s = g_col[beg + i];
            s_src[t] = s;
            float4 el = *(const float4*)(g_el1 + s * 4);
            float e0 = el.x + ern.x; e0 = e0 > 0.f ? e0 : 0.2f * e0;
            float e1 = el.y + ern.y; e1 = e1 > 0.f ? e1 : 0.2f * e1;
            float e2 = el.z + ern.z; e2 = e2 > 0.f ? e2 : 0.2f * e2;
            float e3 = el.w + ern.w; e3 = e3 > 0.f ? e3 : 0.2f * e3;
            s_ex[t][0] = __expf(e0);
            s_ex[t][1] = __expf(e1);
            s_ex[t][2] = __expf(e2);
            s_ex[t][3] = __expf(e3);
        }
        __syncthreads();
        int cnt = min(64, deg - base);
        #pragma unroll 4
        for (int j = 0; j < cnt; j++) {
            const float4* row = (const float4*)(g_feat1 + (size_t)s_src[j] * 256);
            float a = s_ex[j][h];
            float4 v = row[t];
            den   += a;
            acc.x += v.x * a;
            acc.y += v.y * a;
            acc.z += v.z * a;
            acc.w += v.w * a;
        }
        __syncthreads();
    }
    float inv = 1.f / den;
    float4 o;
    o.x = acc.x * inv + bb.x; o.x = o.x > 0.f ? o.x : __expf(o.x) - 1.f;
    o.y = acc.y * inv + bb.y; o.y = o.y > 0.f ? o.y : __expf(o.y) - 1.f;
    o.z = acc.z * inv + bb.z; o.z = o.z > 0.f ? o.z : __expf(o.z) - 1.f;
    o.w = acc.w * inv + bb.w; o.w = o.w > 0.f ? o.w : __expf(o.w) - 1.f;
    ((float4*)(g_h + n * 256))[t] = o;
}

// ---------------- GEMM2 (h @ W2) fused with el2/er2 reduction ----------------
__global__ void __launch_bounds__(256) k_gemm2(const float* __restrict__ W2,
                                               const float* __restrict__ al2,
                                               const float* __restrict__ ar2) {
    __shared__ float Ws[4096];
    __shared__ float Hs[4096];
    int tid = threadIdx.x;
    int nb0 = blockIdx.x * 16;

    const float4* w4 = (const float4*)W2;
    float4* ws4 = (float4*)Ws;
    const float4* h4 = (const float4*)(g_h + nb0 * 256);
    float4* hs4 = (float4*)Hs;
    for (int i = tid; i < 1024; i += 256) { ws4[i] = w4[i]; hs4[i] = h4[i]; }
    __syncthreads();

    int r = tid >> 4, c = tid & 15;
    const float* hr = Hs + r * 256;
    float acc = 0.f;
    #pragma unroll 8
    for (int k = 0; k < 256; k++) acc += hr[k] * Ws[k * 16 + c];

    int node = nb0 + r;
    g_feat2[node * 16 + c] = acc;

    float vl = acc * al2[c];
    float vr = acc * ar2[c];
    #pragma unroll
    for (int o = 8; o; o >>= 1) {
        vl += __shfl_xor_sync(0xffffffffu, vl, o);
        vr += __shfl_xor_sync(0xffffffffu, vr, o);
    }
    if (c == 0) { g_el2[node] = vl; g_er2[node] = vr; }
}

// ---------------- layer-2 softmax-aggregate + bias + log_softmax (warp/node) ------
__global__ void __launch_bounds__(256) k_aggr2(const float* __restrict__ b2,
                                               float* __restrict__ out) {
    int n = (blockIdx.x * blockDim.x + threadIdx.x) >> 5;
    int lane = threadIdx.x & 31;
    if (n >= NN) return;
    int beg = g_off[n], deg = g_off[n + 1] - beg;

    float v;
    if (deg == 0) {
        v = b2[lane & 15];
    } else {
        float ern = g_er2[n];
        int f = lane & 15, half = lane >> 4;
        float acc = 0.f, den = 0.f;
        for (int i = half; i < deg; i += 2) {
            int s = g_col[beg + i];
            float e = g_el2[s] + ern; e = e > 0.f ? e : 0.2f * e;
            float a = __expf(e);
            den += a;
            acc += g_feat2[s * 16 + f] * a;
        }
        acc += __shfl_xor_sync(0xffffffffu, acc, 16);
        den += __shfl_xor_sync(0xffffffffu, den, 16);
        v = acc / den + b2[lane & 15];
    }
    // fused log_softmax over the 16 classes (one per lane in each half-warp)
    float m = v;
    #pragma unroll
    for (int o = 8; o; o >>= 1) m = fmaxf(m, __shfl_xor_sync(0xffffffffu, m, o));
    float s = expf(v - m);
    #pragma unroll
    for (int o = 8; o; o >>= 1) s += __shfl_xor_sync(0xffffffffu, s, o);
    if (lane < 16) out[n * 16 + lane] = v - (m + logf(s));
}

// ---------------- launch ----------------
extern "C" void kernel_launch(void* const* d_in, const int* in_sizes, int n_in,
                              void* d_out, int out_size) {
    const float* x   = (const float*)d_in[0];
    const int*   src = (const int*)d_in[1];
    const int*   dst = (const int*)d_in[2];
    const float* W1  = (const float*)d_in[3];
    const float* al1 = (const float*)d_in[4];
    const float* ar1 = (const float*)d_in[5];
    const float* b1  = (const float*)d_in[6];
    const float* W2  = (const float*)d_in[7];
    const float* al2 = (const float*)d_in[8];
    const float* ar2 = (const float*)d_in[9];
    const float* b2  = (const float*)d_in[10];
    float* out = (float*)d_out;

    static cudaStream_t s2 = nullptr;
    static cudaEvent_t evFork = nullptr, evJoin = nullptr;
    if (!s2) {
        cudaFuncSetAttribute(k_gemm1_mma, cudaFuncAttributeMaxDynamicSharedMemorySize, G1_SMEM);
        cudaStreamCreateWithFlags(&s2, cudaStreamNonBlocking);
        cudaEventCreateWithFlags(&evFork, cudaEventDisableTiming);
        cudaEventCreateWithFlags(&evJoin, cudaEventDisableTiming);
    }

    // fork: CSR build chain on s2, dense chain on the main stream
    cudaEventRecord(evFork, 0);
    cudaStreamWaitEvent(s2, evFork, 0);

    k_clear<<<(NN + 255) / 256, 256, 0, s2>>>();
    k_hist<<<(EE + 255) / 256, 256, 0, s2>>>(dst);
    k_scan<<<1, 1024, 0, s2>>>();
    k_scatter<<<(EE + 255) / 256, 256, 0, s2>>>(src, dst);
    cudaEventRecord(evJoin, s2);

    // dense chain (independent of CSR)
    k_cvt_x<<<(NN * NF) / 256, 256>>>(x);
    k_cvt_w<<<(NF * NF) / 256, 256>>>(W1);
    k_gemm1_mma<<<dim3(NF / BN, NPAD / BM), 256, G1_SMEM>>>();
    k_el1<<<(NN * NH + 255) / 256, 256>>>(al1, ar1);

    // join: aggregation needs both CSR and feat1/el1
    cudaStreamWaitEvent(0, evJoin, 0);

    k_aggr1<<<NN, 64>>>(b1);
    k_gemm2<<<NN / 16, 256>>>(W2, al2, ar2);
    k_aggr2<<<(NN * 32 + 255) / 256, 256>>>(b2, out);
}